// round 3
// baseline (speedup 1.0000x reference)
#include <cuda_runtime.h>
#include <cuda_bf16.h>
#include <cstdint>

#define INV_SQRT3 0.57735026918962576451f
#define INV_SQRT2 0.70710678118654752440f
#define LN_EPS 1e-5f

#define MAX_NODES 16384
#define MAX_EDGES 131072

// scratch (allocation-free rule: __device__ globals)
__device__ int g_hist[MAX_NODES];
__device__ int g_cursor[MAX_NODES];
__device__ int g_start[MAX_NODES + 1];
__device__ int g_sorted[MAX_EDGES];

__device__ __forceinline__ float warp_sum(float v) {
    v += __shfl_xor_sync(0xffffffffu, v, 16);
    v += __shfl_xor_sync(0xffffffffu, v, 8);
    v += __shfl_xor_sync(0xffffffffu, v, 4);
    v += __shfl_xor_sync(0xffffffffu, v, 2);
    v += __shfl_xor_sync(0xffffffffu, v, 1);
    return v;
}

// ---------------------------------------------------------------------------
// Sort pipeline: counting sort of edge ids by edge_dst
// ---------------------------------------------------------------------------
__global__ void hist_zero_kernel(int n_nodes) {
    int i = blockIdx.x * blockDim.x + threadIdx.x;
    if (i < n_nodes) g_hist[i] = 0;
}

__global__ void hist_count_kernel(const int* __restrict__ edge_dst, int n_edges) {
    int i = blockIdx.x * blockDim.x + threadIdx.x;
    if (i < n_edges) atomicAdd(&g_hist[edge_dst[i]], 1);
}

// single block, 1024 threads, 16 bins per thread (covers 16384 nodes)
__global__ void __launch_bounds__(1024) scan_kernel(int n_nodes) {
    __shared__ int ssum[1024];
    const int t = threadIdx.x;
    const int base = t * 16;

    int v[16];
    int s = 0;
#pragma unroll
    for (int i = 0; i < 16; i++) {
        int idx = base + i;
        v[i] = (idx < n_nodes) ? g_hist[idx] : 0;
        s += v[i];
    }
    ssum[t] = s;
    __syncthreads();

    for (int off = 1; off < 1024; off <<= 1) {
        int x = (t >= off) ? ssum[t - off] : 0;
        __syncthreads();
        ssum[t] += x;
        __syncthreads();
    }

    int run = (t == 0) ? 0 : ssum[t - 1];  // exclusive base
#pragma unroll
    for (int i = 0; i < 16; i++) {
        int idx = base + i;
        if (idx < n_nodes) {
            g_start[idx] = run;
            g_cursor[idx] = run;
        }
        run += v[i];
    }
    if (t == 1023) g_start[n_nodes] = run;
}

__global__ void scatter_kernel(const int* __restrict__ edge_dst, int n_edges) {
    int i = blockIdx.x * blockDim.x + threadIdx.x;
    if (i < n_edges) {
        int pos = atomicAdd(&g_cursor[edge_dst[i]], 1);
        g_sorted[pos] = i;
    }
}

// ---------------------------------------------------------------------------
// Fused gather + depthwise TP + bias + equivariant LN. One warp per node.
// Index chain (sorted-id -> src -> sh) prefetched one-edge-per-lane, then
// shuffle-broadcast in the inner loop so the 9 bulk loads per edge have
// no dependent-latency chain in front of them.
// ---------------------------------------------------------------------------
__global__ void __launch_bounds__(256) fused_tp_ln_kernel(
    const float* __restrict__ node_feat,   // (N, 320)
    const float* __restrict__ edge_sh,     // (E, 4)
    const float* __restrict__ edge_weight, // (E, 448)
    const float* __restrict__ tp_bias,     // (192,)
    const int*   __restrict__ edge_src,
    const float* __restrict__ lnw,         // (448,)
    const float* __restrict__ lnb,         // (192,)
    float*       __restrict__ out,         // (N, 960)
    int n_nodes)
{
    const int warp = (blockIdx.x * blockDim.x + threadIdx.x) >> 5;
    const int lane = threadIdx.x & 31;
    if (warp >= n_nodes) return;
    const int node = warp;

    const int beg = g_start[node];
    const int end = g_start[node + 1];
    const int deg = end - beg;

    float a0x = 0.f, a0y = 0.f, a0z = 0.f, a0w = 0.f;  // out0a
    float ob0 = 0.f, ob1 = 0.f;                         // out0b
    float A[12];                                        // out1a
    float B[6];                                         // out1b
    float C[6];                                         // out1c
#pragma unroll
    for (int i = 0; i < 12; i++) A[i] = 0.f;
#pragma unroll
    for (int i = 0; i < 6; i++) { B[i] = 0.f; C[i] = 0.f; }

    for (int base = beg; base < end; base += 32) {
        const int cnt = min(32, end - base);

        // prefetch index chain: one edge per lane, all in parallel
        int   e_l = 0, s_l = 0;
        float4 sh_l = make_float4(0.f, 0.f, 0.f, 0.f);
        if (lane < cnt) {
            e_l  = __ldg(g_sorted + base + lane);
            s_l  = __ldg(edge_src + e_l);
            sh_l = __ldg(reinterpret_cast<const float4*>(edge_sh) + e_l);
        }

        for (int j = 0; j < cnt; j++) {
            const int e = __shfl_sync(0xffffffffu, e_l, j);
            const int s = __shfl_sync(0xffffffffu, s_l, j);
            const float ys  = __shfl_sync(0xffffffffu, sh_l.x, j);
            const float yv0 = __shfl_sync(0xffffffffu, sh_l.y, j);
            const float yv1 = __shfl_sync(0xffffffffu, sh_l.z, j);
            const float yv2 = __shfl_sync(0xffffffffu, sh_l.w, j);

            const float* xrow = node_feat + (size_t)s * 320u;
            const float* wrow = edge_weight + (size_t)e * 448u;

            // issue all loads up front (independent addresses)
            const float4 xs = __ldg(reinterpret_cast<const float4*>(xrow + 4 * lane));
            const float4 w0 = __ldg(reinterpret_cast<const float4*>(wrow + 4 * lane));
            const float4 w1 = __ldg(reinterpret_cast<const float4*>(wrow + 128 + 4 * lane));
            const float2 w2 = __ldg(reinterpret_cast<const float2*>(wrow + 256 + 2 * lane));
            const float2 w3 = __ldg(reinterpret_cast<const float2*>(wrow + 320 + 2 * lane));
            const float2 w4 = __ldg(reinterpret_cast<const float2*>(wrow + 384 + 2 * lane));
            const float2 p0 = __ldg(reinterpret_cast<const float2*>(xrow + 128 + 6 * lane));
            const float2 p1 = __ldg(reinterpret_cast<const float2*>(xrow + 128 + 6 * lane + 2));
            const float2 p2 = __ldg(reinterpret_cast<const float2*>(xrow + 128 + 6 * lane + 4));

            a0x += w0.x * xs.x * ys;
            a0y += w0.y * xs.y * ys;
            a0z += w0.z * xs.z * ys;
            a0w += w0.w * xs.w * ys;

            const float t0 = w1.x * xs.x, t1 = w1.y * xs.y;
            const float t2 = w1.z * xs.z, t3 = w1.w * xs.w;
            A[0] += t0 * yv0; A[1]  += t0 * yv1; A[2]  += t0 * yv2;
            A[3] += t1 * yv0; A[4]  += t1 * yv1; A[5]  += t1 * yv2;
            A[6] += t2 * yv0; A[7]  += t2 * yv1; A[8]  += t2 * yv2;
            A[9] += t3 * yv0; A[10] += t3 * yv1; A[11] += t3 * yv2;

            // xv[v0] = (p0.x, p0.y, p1.x) ; xv[v1] = (p1.y, p2.x, p2.y)
            const float d0 = p0.x * yv0 + p0.y * yv1 + p1.x * yv2;
            const float d1 = p1.y * yv0 + p2.x * yv1 + p2.y * yv2;
            ob0 += w3.x * d0 * INV_SQRT3;
            ob1 += w3.y * d1 * INV_SQRT3;

            const float c0 = w2.x * ys, c1 = w2.y * ys;
            B[0] += c0 * p0.x; B[1] += c0 * p0.y; B[2] += c0 * p1.x;
            B[3] += c1 * p1.y; B[4] += c1 * p2.x; B[5] += c1 * p2.y;

            const float k0 = w4.x * INV_SQRT2, k1 = w4.y * INV_SQRT2;
            C[0] += k0 * (p0.y * yv2 - p1.x * yv1);
            C[1] += k0 * (p1.x * yv0 - p0.x * yv2);
            C[2] += k0 * (p0.x * yv1 - p0.y * yv0);
            C[3] += k1 * (p2.x * yv2 - p2.y * yv1);
            C[4] += k1 * (p2.y * yv0 - p1.y * yv2);
            C[5] += k1 * (p1.y * yv1 - p2.x * yv0);
        }
    }

    // per-edge bias, summed over deg edges
    const float fdeg = (float)deg;
    {
        const float4 b0 = __ldg(reinterpret_cast<const float4*>(tp_bias + 4 * lane));
        a0x += fdeg * b0.x; a0y += fdeg * b0.y;
        a0z += fdeg * b0.z; a0w += fdeg * b0.w;
        const float2 bb = __ldg(reinterpret_cast<const float2*>(tp_bias + 128 + 2 * lane));
        ob0 += fdeg * bb.x; ob1 += fdeg * bb.y;
    }

    // ---- equivariant LayerNorm on register-resident row ---------------------
    float s0 = a0x + a0y + a0z + a0w;
    float q0 = a0x * a0x + a0y * a0y + a0z * a0z + a0w * a0w;
    float s1 = ob0 + ob1;
    float q1 = ob0 * ob0 + ob1 * ob1;
    float q2 = 0.f, q3 = 0.f, q4 = 0.f;
#pragma unroll
    for (int i = 0; i < 12; i++) q2 += A[i] * A[i];
#pragma unroll
    for (int i = 0; i < 6; i++) { q3 += B[i] * B[i]; q4 += C[i] * C[i]; }

    s0 = warp_sum(s0); q0 = warp_sum(q0);
    s1 = warp_sum(s1); q1 = warp_sum(q1);
    q2 = warp_sum(q2); q3 = warp_sum(q3); q4 = warp_sum(q4);

    const float mu0 = s0 * (1.f / 128.f);
    const float r0  = rsqrtf(fmaxf(q0 * (1.f / 128.f) - mu0 * mu0, 0.f) + LN_EPS);
    const float mu1 = s1 * (1.f / 64.f);
    const float r1  = rsqrtf(fmaxf(q1 * (1.f / 64.f) - mu1 * mu1, 0.f) + LN_EPS);
    const float r2  = rsqrtf(q2 * (1.f / 384.f) + LN_EPS);
    const float r3  = rsqrtf(q3 * (1.f / 192.f) + LN_EPS);
    const float r4  = rsqrtf(q4 * (1.f / 192.f) + LN_EPS);

    float* row = out + (size_t)node * 960u;

    {   // field0
        const float4 wv = __ldg(reinterpret_cast<const float4*>(lnw + 4 * lane));
        const float4 bv = __ldg(reinterpret_cast<const float4*>(lnb + 4 * lane));
        float4 o;
        o.x = (a0x - mu0) * r0 * wv.x + bv.x;
        o.y = (a0y - mu0) * r0 * wv.y + bv.y;
        o.z = (a0z - mu0) * r0 * wv.z + bv.z;
        o.w = (a0w - mu0) * r0 * wv.w + bv.w;
        *reinterpret_cast<float4*>(row + 4 * lane) = o;
    }
    {   // field1
        const float2 wv = __ldg(reinterpret_cast<const float2*>(lnw + 128 + 2 * lane));
        const float2 bv = __ldg(reinterpret_cast<const float2*>(lnb + 128 + 2 * lane));
        float2 o;
        o.x = (ob0 - mu1) * r1 * wv.x + bv.x;
        o.y = (ob1 - mu1) * r1 * wv.y + bv.y;
        *reinterpret_cast<float2*>(row + 128 + 2 * lane) = o;
    }
    {   // field2: channels u = 4*lane + {0..3}
        const float4 wv = __ldg(reinterpret_cast<const float4*>(lnw + 192 + 4 * lane));
        const float sa = wv.x * r2, sb = wv.y * r2, sc = wv.z * r2, sd = wv.w * r2;
        float4 o1 = make_float4(A[0] * sa, A[1] * sa, A[2]  * sa, A[3]  * sb);
        float4 o2 = make_float4(A[4] * sb, A[5] * sb, A[6]  * sc, A[7]  * sc);
        float4 o3 = make_float4(A[8] * sc, A[9] * sd, A[10] * sd, A[11] * sd);
        *reinterpret_cast<float4*>(row + 192 + 12 * lane)     = o1;
        *reinterpret_cast<float4*>(row + 192 + 12 * lane + 4) = o2;
        *reinterpret_cast<float4*>(row + 192 + 12 * lane + 8) = o3;
    }
    {   // field3
        const float2 wv = __ldg(reinterpret_cast<const float2*>(lnw + 320 + 2 * lane));
        const float sa = wv.x * r3, sb = wv.y * r3;
        float2 o1 = make_float2(B[0] * sa, B[1] * sa);
        float2 o2 = make_float2(B[2] * sa, B[3] * sb);
        float2 o3 = make_float2(B[4] * sb, B[5] * sb);
        *reinterpret_cast<float2*>(row + 576 + 6 * lane)     = o1;
        *reinterpret_cast<float2*>(row + 576 + 6 * lane + 2) = o2;
        *reinterpret_cast<float2*>(row + 576 + 6 * lane + 4) = o3;
    }
    {   // field4
        const float2 wv = __ldg(reinterpret_cast<const float2*>(lnw + 384 + 2 * lane));
        const float sa = wv.x * r4, sb = wv.y * r4;
        float2 o1 = make_float2(C[0] * sa, C[1] * sa);
        float2 o2 = make_float2(C[2] * sa, C[3] * sb);
        float2 o3 = make_float2(C[4] * sb, C[5] * sb);
        *reinterpret_cast<float2*>(row + 768 + 6 * lane)     = o1;
        *reinterpret_cast<float2*>(row + 768 + 6 * lane + 2) = o2;
        *reinterpret_cast<float2*>(row + 768 + 6 * lane + 4) = o3;
    }
}

// ---------------------------------------------------------------------------
extern "C" void kernel_launch(void* const* d_in, const int* in_sizes, int n_in,
                              void* d_out, int out_size)
{
    const float* node_feat   = (const float*)d_in[0];
    const float* edge_sh     = (const float*)d_in[1];
    const float* edge_weight = (const float*)d_in[2];
    const float* tp_bias     = (const float*)d_in[3];
    const float* ln_weight   = (const float*)d_in[4];
    const float* ln_bias     = (const float*)d_in[5];
    const int*   edge_src    = (const int*)d_in[6];
    const int*   edge_dst    = (const int*)d_in[7];
    float* out = (float*)d_out;

    const int n_nodes = in_sizes[0] / 320;
    const int n_edges = in_sizes[7];

    hist_zero_kernel<<<(n_nodes + 255) / 256, 256>>>(n_nodes);
    hist_count_kernel<<<(n_edges + 255) / 256, 256>>>(edge_dst, n_edges);
    scan_kernel<<<1, 1024>>>(n_nodes);
    scatter_kernel<<<(n_edges + 255) / 256, 256>>>(edge_dst, n_edges);

    const int warps_per_block = 256 / 32;
    const int blocks = (n_nodes + warps_per_block - 1) / warps_per_block;
    fused_tp_ln_kernel<<<blocks, 256>>>(node_feat, edge_sh, edge_weight,
                                        tp_bias, edge_src, ln_weight, ln_bias,
                                        out, n_nodes);
}

// round 4
// speedup vs baseline: 1.0537x; 1.0537x over previous
#include <cuda_runtime.h>
#include <cuda_bf16.h>
#include <cstdint>

#define INV_SQRT3 0.57735026918962576451f
#define INV_SQRT2 0.70710678118654752440f
#define LN_EPS 1e-5f

#define MAX_NODES 16384
#define MAX_EDGES 131072

// scratch (allocation-free rule: __device__ globals)
__device__ int g_hist[MAX_NODES];
__device__ int g_rank[MAX_EDGES];
__device__ int g_start[MAX_NODES + 1];
__device__ int g_sorted[MAX_EDGES];

__device__ __forceinline__ float warp_sum(float v) {
    v += __shfl_xor_sync(0xffffffffu, v, 16);
    v += __shfl_xor_sync(0xffffffffu, v, 8);
    v += __shfl_xor_sync(0xffffffffu, v, 4);
    v += __shfl_xor_sync(0xffffffffu, v, 2);
    v += __shfl_xor_sync(0xffffffffu, v, 1);
    return v;
}

// ---------------------------------------------------------------------------
// Sort pipeline: counting sort of edge ids by edge_dst (rank-based, one atomic pass)
// ---------------------------------------------------------------------------
__global__ void hist_zero_kernel(int n_nodes) {
    int i = blockIdx.x * blockDim.x + threadIdx.x;
    if (i < n_nodes) g_hist[i] = 0;
}

__global__ void hist_count_kernel(const int* __restrict__ edge_dst, int n_edges) {
    int i = blockIdx.x * blockDim.x + threadIdx.x;
    if (i < n_edges) {
        g_rank[i] = atomicAdd(&g_hist[edge_dst[i]], 1);
    }
}

// single block, 1024 threads, 16 bins per thread (covers 16384 nodes)
__global__ void __launch_bounds__(1024) scan_kernel(int n_nodes) {
    __shared__ int ssum[1024];
    const int t = threadIdx.x;
    const int base = t * 16;

    int v[16];
    int s = 0;
#pragma unroll
    for (int i = 0; i < 16; i++) {
        int idx = base + i;
        v[i] = (idx < n_nodes) ? g_hist[idx] : 0;
        s += v[i];
    }
    ssum[t] = s;
    __syncthreads();

    for (int off = 1; off < 1024; off <<= 1) {
        int x = (t >= off) ? ssum[t - off] : 0;
        __syncthreads();
        ssum[t] += x;
        __syncthreads();
    }

    int run = (t == 0) ? 0 : ssum[t - 1];  // exclusive base
#pragma unroll
    for (int i = 0; i < 16; i++) {
        int idx = base + i;
        if (idx < n_nodes) g_start[idx] = run;
        run += v[i];
    }
    if (t == 1023) g_start[n_nodes] = run;
}

// atomic-free scatter using precomputed rank
__global__ void scatter_kernel(const int* __restrict__ edge_dst, int n_edges) {
    int i = blockIdx.x * blockDim.x + threadIdx.x;
    if (i < n_edges) {
        g_sorted[g_start[edge_dst[i]] + g_rank[i]] = i;
    }
}

// ---------------------------------------------------------------------------
// Fused gather + depthwise TP + bias + equivariant LN. One warp per node.
// The two-level index chase (g_sorted -> edge_src) for edge i+1 is
// software-pipelined behind edge i's bulk loads and math.
// ---------------------------------------------------------------------------
__global__ void __launch_bounds__(256) fused_tp_ln_kernel(
    const float* __restrict__ node_feat,   // (N, 320)
    const float* __restrict__ edge_sh,     // (E, 4)
    const float* __restrict__ edge_weight, // (E, 448)
    const float* __restrict__ tp_bias,     // (192,)
    const int*   __restrict__ edge_src,
    const float* __restrict__ lnw,         // (448,)
    const float* __restrict__ lnb,         // (192,)
    float*       __restrict__ out,         // (N, 960)
    int n_nodes)
{
    const int warp = (blockIdx.x * blockDim.x + threadIdx.x) >> 5;
    const int lane = threadIdx.x & 31;
    if (warp >= n_nodes) return;
    const int node = warp;

    const int beg = g_start[node];
    const int end = g_start[node + 1];
    const int deg = end - beg;

    float a0x = 0.f, a0y = 0.f, a0z = 0.f, a0w = 0.f;  // out0a
    float ob0 = 0.f, ob1 = 0.f;                         // out0b
    float A[12];                                        // out1a
    float B[6];                                         // out1b
    float C[6];                                         // out1c
#pragma unroll
    for (int i = 0; i < 12; i++) A[i] = 0.f;
#pragma unroll
    for (int i = 0; i < 6; i++) { B[i] = 0.f; C[i] = 0.f; }

    // prologue of the index-chase pipeline
    int e_cur = 0, s_cur = 0;
    if (deg > 0) {
        e_cur = __ldg(g_sorted + beg);
        s_cur = __ldg(edge_src + e_cur);
    }

    for (int ei = beg; ei < end; ei++) {
        const int e = e_cur;
        const int s = s_cur;

        // prefetch next edge's index chain (overlaps with this edge's work)
        if (ei + 1 < end) {
            e_cur = __ldg(g_sorted + ei + 1);
            s_cur = __ldg(edge_src + e_cur);
        }

        const float4 shv = __ldg(reinterpret_cast<const float4*>(edge_sh) + e);
        const float ys = shv.x, yv0 = shv.y, yv1 = shv.z, yv2 = shv.w;

        const float* xrow = node_feat + (size_t)s * 320u;
        const float* wrow = edge_weight + (size_t)e * 448u;

        const float4 xs = __ldg(reinterpret_cast<const float4*>(xrow + 4 * lane));
        const float4 w0 = __ldg(reinterpret_cast<const float4*>(wrow + 4 * lane));
        const float4 w1 = __ldg(reinterpret_cast<const float4*>(wrow + 128 + 4 * lane));
        const float2 w2 = __ldg(reinterpret_cast<const float2*>(wrow + 256 + 2 * lane));
        const float2 w3 = __ldg(reinterpret_cast<const float2*>(wrow + 320 + 2 * lane));
        const float2 w4 = __ldg(reinterpret_cast<const float2*>(wrow + 384 + 2 * lane));
        const float2 p0 = __ldg(reinterpret_cast<const float2*>(xrow + 128 + 6 * lane));
        const float2 p1 = __ldg(reinterpret_cast<const float2*>(xrow + 128 + 6 * lane + 2));
        const float2 p2 = __ldg(reinterpret_cast<const float2*>(xrow + 128 + 6 * lane + 4));

        a0x += w0.x * xs.x * ys;
        a0y += w0.y * xs.y * ys;
        a0z += w0.z * xs.z * ys;
        a0w += w0.w * xs.w * ys;

        const float t0 = w1.x * xs.x, t1 = w1.y * xs.y;
        const float t2 = w1.z * xs.z, t3 = w1.w * xs.w;
        A[0] += t0 * yv0; A[1]  += t0 * yv1; A[2]  += t0 * yv2;
        A[3] += t1 * yv0; A[4]  += t1 * yv1; A[5]  += t1 * yv2;
        A[6] += t2 * yv0; A[7]  += t2 * yv1; A[8]  += t2 * yv2;
        A[9] += t3 * yv0; A[10] += t3 * yv1; A[11] += t3 * yv2;

        // xv[v0] = (p0.x, p0.y, p1.x) ; xv[v1] = (p1.y, p2.x, p2.y)
        const float d0 = p0.x * yv0 + p0.y * yv1 + p1.x * yv2;
        const float d1 = p1.y * yv0 + p2.x * yv1 + p2.y * yv2;
        ob0 += w3.x * d0 * INV_SQRT3;
        ob1 += w3.y * d1 * INV_SQRT3;

        const float c0 = w2.x * ys, c1 = w2.y * ys;
        B[0] += c0 * p0.x; B[1] += c0 * p0.y; B[2] += c0 * p1.x;
        B[3] += c1 * p1.y; B[4] += c1 * p2.x; B[5] += c1 * p2.y;

        const float k0 = w4.x * INV_SQRT2, k1 = w4.y * INV_SQRT2;
        C[0] += k0 * (p0.y * yv2 - p1.x * yv1);
        C[1] += k0 * (p1.x * yv0 - p0.x * yv2);
        C[2] += k0 * (p0.x * yv1 - p0.y * yv0);
        C[3] += k1 * (p2.x * yv2 - p2.y * yv1);
        C[4] += k1 * (p2.y * yv0 - p1.y * yv2);
        C[5] += k1 * (p1.y * yv1 - p2.x * yv0);
    }

    // per-edge bias, summed over deg edges
    const float fdeg = (float)deg;
    {
        const float4 b0 = __ldg(reinterpret_cast<const float4*>(tp_bias + 4 * lane));
        a0x += fdeg * b0.x; a0y += fdeg * b0.y;
        a0z += fdeg * b0.z; a0w += fdeg * b0.w;
        const float2 bb = __ldg(reinterpret_cast<const float2*>(tp_bias + 128 + 2 * lane));
        ob0 += fdeg * bb.x; ob1 += fdeg * bb.y;
    }

    // ---- equivariant LayerNorm on register-resident row ---------------------
    float s0 = a0x + a0y + a0z + a0w;
    float q0 = a0x * a0x + a0y * a0y + a0z * a0z + a0w * a0w;
    float s1 = ob0 + ob1;
    float q1 = ob0 * ob0 + ob1 * ob1;
    float q2 = 0.f, q3 = 0.f, q4 = 0.f;
#pragma unroll
    for (int i = 0; i < 12; i++) q2 += A[i] * A[i];
#pragma unroll
    for (int i = 0; i < 6; i++) { q3 += B[i] * B[i]; q4 += C[i] * C[i]; }

    s0 = warp_sum(s0); q0 = warp_sum(q0);
    s1 = warp_sum(s1); q1 = warp_sum(q1);
    q2 = warp_sum(q2); q3 = warp_sum(q3); q4 = warp_sum(q4);

    const float mu0 = s0 * (1.f / 128.f);
    const float r0  = rsqrtf(fmaxf(q0 * (1.f / 128.f) - mu0 * mu0, 0.f) + LN_EPS);
    const float mu1 = s1 * (1.f / 64.f);
    const float r1  = rsqrtf(fmaxf(q1 * (1.f / 64.f) - mu1 * mu1, 0.f) + LN_EPS);
    const float r2  = rsqrtf(q2 * (1.f / 384.f) + LN_EPS);
    const float r3  = rsqrtf(q3 * (1.f / 192.f) + LN_EPS);
    const float r4  = rsqrtf(q4 * (1.f / 192.f) + LN_EPS);

    float* row = out + (size_t)node * 960u;

    {   // field0
        const float4 wv = __ldg(reinterpret_cast<const float4*>(lnw + 4 * lane));
        const float4 bv = __ldg(reinterpret_cast<const float4*>(lnb + 4 * lane));
        float4 o;
        o.x = (a0x - mu0) * r0 * wv.x + bv.x;
        o.y = (a0y - mu0) * r0 * wv.y + bv.y;
        o.z = (a0z - mu0) * r0 * wv.z + bv.z;
        o.w = (a0w - mu0) * r0 * wv.w + bv.w;
        *reinterpret_cast<float4*>(row + 4 * lane) = o;
    }
    {   // field1
        const float2 wv = __ldg(reinterpret_cast<const float2*>(lnw + 128 + 2 * lane));
        const float2 bv = __ldg(reinterpret_cast<const float2*>(lnb + 128 + 2 * lane));
        float2 o;
        o.x = (ob0 - mu1) * r1 * wv.x + bv.x;
        o.y = (ob1 - mu1) * r1 * wv.y + bv.y;
        *reinterpret_cast<float2*>(row + 128 + 2 * lane) = o;
    }
    {   // field2: channels u = 4*lane + {0..3}
        const float4 wv = __ldg(reinterpret_cast<const float4*>(lnw + 192 + 4 * lane));
        const float sa = wv.x * r2, sb = wv.y * r2, sc = wv.z * r2, sd = wv.w * r2;
        float4 o1 = make_float4(A[0] * sa, A[1] * sa, A[2]  * sa, A[3]  * sb);
        float4 o2 = make_float4(A[4] * sb, A[5] * sb, A[6]  * sc, A[7]  * sc);
        float4 o3 = make_float4(A[8] * sc, A[9] * sd, A[10] * sd, A[11] * sd);
        *reinterpret_cast<float4*>(row + 192 + 12 * lane)     = o1;
        *reinterpret_cast<float4*>(row + 192 + 12 * lane + 4) = o2;
        *reinterpret_cast<float4*>(row + 192 + 12 * lane + 8) = o3;
    }
    {   // field3
        const float2 wv = __ldg(reinterpret_cast<const float2*>(lnw + 320 + 2 * lane));
        const float sa = wv.x * r3, sb = wv.y * r3;
        float2 o1 = make_float2(B[0] * sa, B[1] * sa);
        float2 o2 = make_float2(B[2] * sa, B[3] * sb);
        float2 o3 = make_float2(B[4] * sb, B[5] * sb);
        *reinterpret_cast<float2*>(row + 576 + 6 * lane)     = o1;
        *reinterpret_cast<float2*>(row + 576 + 6 * lane + 2) = o2;
        *reinterpret_cast<float2*>(row + 576 + 6 * lane + 4) = o3;
    }
    {   // field4
        const float2 wv = __ldg(reinterpret_cast<const float2*>(lnw + 384 + 2 * lane));
        const float sa = wv.x * r4, sb = wv.y * r4;
        float2 o1 = make_float2(C[0] * sa, C[1] * sa);
        float2 o2 = make_float2(C[2] * sa, C[3] * sb);
        float2 o3 = make_float2(C[4] * sb, C[5] * sb);
        *reinterpret_cast<float2*>(row + 768 + 6 * lane)     = o1;
        *reinterpret_cast<float2*>(row + 768 + 6 * lane + 2) = o2;
        *reinterpret_cast<float2*>(row + 768 + 6 * lane + 4) = o3;
    }
}

// ---------------------------------------------------------------------------
extern "C" void kernel_launch(void* const* d_in, const int* in_sizes, int n_in,
                              void* d_out, int out_size)
{
    const float* node_feat   = (const float*)d_in[0];
    const float* edge_sh     = (const float*)d_in[1];
    const float* edge_weight = (const float*)d_in[2];
    const float* tp_bias     = (const float*)d_in[3];
    const float* ln_weight   = (const float*)d_in[4];
    const float* ln_bias     = (const float*)d_in[5];
    const int*   edge_src    = (const int*)d_in[6];
    const int*   edge_dst    = (const int*)d_in[7];
    float* out = (float*)d_out;

    const int n_nodes = in_sizes[0] / 320;
    const int n_edges = in_sizes[7];

    hist_zero_kernel<<<(n_nodes + 255) / 256, 256>>>(n_nodes);
    hist_count_kernel<<<(n_edges + 255) / 256, 256>>>(edge_dst, n_edges);
    scan_kernel<<<1, 1024>>>(n_nodes);
    scatter_kernel<<<(n_edges + 255) / 256, 256>>>(edge_dst, n_edges);

    const int warps_per_block = 256 / 32;
    const int blocks = (n_nodes + warps_per_block - 1) / warps_per_block;
    fused_tp_ln_kernel<<<blocks, 256>>>(node_feat, edge_sh, edge_weight,
                                        tp_bias, edge_src, ln_weight, ln_bias,
                                        out, n_nodes);
}

// round 5
// speedup vs baseline: 1.3169x; 1.2498x over previous
#include <cuda_runtime.h>
#include <cuda_bf16.h>
#include <cstdint>

#define INV_SQRT3 0.57735026918962576451f
#define INV_SQRT2 0.70710678118654752440f
#define LN_EPS 1e-5f

#define MAX_NODES 16384
#define MAX_EDGES 131072

// scratch (allocation-free rule: __device__ globals)
__device__ int g_hist[MAX_NODES];
__device__ int g_rank[MAX_EDGES];
__device__ int g_start[MAX_NODES + 1];
__device__ int g_sorted[MAX_EDGES];

__device__ __forceinline__ float warp_sum(float v) {
    v += __shfl_xor_sync(0xffffffffu, v, 16);
    v += __shfl_xor_sync(0xffffffffu, v, 8);
    v += __shfl_xor_sync(0xffffffffu, v, 4);
    v += __shfl_xor_sync(0xffffffffu, v, 2);
    v += __shfl_xor_sync(0xffffffffu, v, 1);
    return v;
}

// ---------------------------------------------------------------------------
// Sort pipeline: counting sort of edge ids by edge_dst (rank-based)
// ---------------------------------------------------------------------------
__global__ void hist_zero_kernel(int n_nodes) {
    int i = blockIdx.x * blockDim.x + threadIdx.x;
    if (i < n_nodes) g_hist[i] = 0;
}

// 4 edges per thread, vectorized edge_dst load
__global__ void hist_count_kernel(const int* __restrict__ edge_dst, int n_edges) {
    int i4 = (blockIdx.x * blockDim.x + threadIdx.x) * 4;
    if (i4 + 3 < n_edges) {
        const int4 d = *reinterpret_cast<const int4*>(edge_dst + i4);
        g_rank[i4 + 0] = atomicAdd(&g_hist[d.x], 1);
        g_rank[i4 + 1] = atomicAdd(&g_hist[d.y], 1);
        g_rank[i4 + 2] = atomicAdd(&g_hist[d.z], 1);
        g_rank[i4 + 3] = atomicAdd(&g_hist[d.w], 1);
    } else {
        for (int i = i4; i < n_edges; i++)
            g_rank[i] = atomicAdd(&g_hist[edge_dst[i]], 1);
    }
}

// single block, 1024 threads, 16 bins per thread (covers 16384 nodes)
__global__ void __launch_bounds__(1024) scan_kernel(int n_nodes) {
    __shared__ int ssum[1024];
    const int t = threadIdx.x;
    const int base = t * 16;

    int v[16];
    int s = 0;
#pragma unroll
    for (int i = 0; i < 16; i++) {
        int idx = base + i;
        v[i] = (idx < n_nodes) ? g_hist[idx] : 0;
        s += v[i];
    }
    ssum[t] = s;
    __syncthreads();

    for (int off = 1; off < 1024; off <<= 1) {
        int x = (t >= off) ? ssum[t - off] : 0;
        __syncthreads();
        ssum[t] += x;
        __syncthreads();
    }

    int run = (t == 0) ? 0 : ssum[t - 1];  // exclusive base
#pragma unroll
    for (int i = 0; i < 16; i++) {
        int idx = base + i;
        if (idx < n_nodes) g_start[idx] = run;
        run += v[i];
    }
    if (t == 1023) g_start[n_nodes] = run;
}

// atomic-free scatter using precomputed rank; 4 edges per thread
__global__ void scatter_kernel(const int* __restrict__ edge_dst, int n_edges) {
    int i4 = (blockIdx.x * blockDim.x + threadIdx.x) * 4;
    if (i4 + 3 < n_edges) {
        const int4 d = *reinterpret_cast<const int4*>(edge_dst + i4);
        const int4 r = *reinterpret_cast<const int4*>(g_rank + i4);
        const int p0 = __ldg(g_start + d.x) + r.x;
        const int p1 = __ldg(g_start + d.y) + r.y;
        const int p2 = __ldg(g_start + d.z) + r.z;
        const int p3 = __ldg(g_start + d.w) + r.w;
        g_sorted[p0] = i4 + 0;
        g_sorted[p1] = i4 + 1;
        g_sorted[p2] = i4 + 2;
        g_sorted[p3] = i4 + 3;
    } else {
        for (int i = i4; i < n_edges; i++)
            g_sorted[g_start[edge_dst[i]] + g_rank[i]] = i;
    }
}

// ---------------------------------------------------------------------------
// Per-edge loaded operands + accumulation helpers
// ---------------------------------------------------------------------------
struct EdgeAcc {
    float a0x, a0y, a0z, a0w;   // out0a
    float ob0, ob1;             // out0b
    float A[12];                // out1a
    float B[6];                 // out1b
    float C[6];                 // out1c
};

struct EdgeData {
    float4 sh;
    float4 xs, w0, w1;
    float2 w2, w3, w4, p0, p1, p2;

    __device__ __forceinline__ void load(const float* __restrict__ node_feat,
                                         const float* __restrict__ edge_sh,
                                         const float* __restrict__ edge_weight,
                                         int e, int s, int lane) {
        sh = __ldg(reinterpret_cast<const float4*>(edge_sh) + e);
        const float* xrow = node_feat + (size_t)s * 320u;
        const float* wrow = edge_weight + (size_t)e * 448u;
        xs = __ldg(reinterpret_cast<const float4*>(xrow + 4 * lane));
        w0 = __ldg(reinterpret_cast<const float4*>(wrow + 4 * lane));
        w1 = __ldg(reinterpret_cast<const float4*>(wrow + 128 + 4 * lane));
        w2 = __ldg(reinterpret_cast<const float2*>(wrow + 256 + 2 * lane));
        w3 = __ldg(reinterpret_cast<const float2*>(wrow + 320 + 2 * lane));
        w4 = __ldg(reinterpret_cast<const float2*>(wrow + 384 + 2 * lane));
        p0 = __ldg(reinterpret_cast<const float2*>(xrow + 128 + 6 * lane));
        p1 = __ldg(reinterpret_cast<const float2*>(xrow + 128 + 6 * lane + 2));
        p2 = __ldg(reinterpret_cast<const float2*>(xrow + 128 + 6 * lane + 4));
    }

    __device__ __forceinline__ void accum(EdgeAcc& ac) const {
        const float ys = sh.x, yv0 = sh.y, yv1 = sh.z, yv2 = sh.w;

        ac.a0x += w0.x * xs.x * ys;
        ac.a0y += w0.y * xs.y * ys;
        ac.a0z += w0.z * xs.z * ys;
        ac.a0w += w0.w * xs.w * ys;

        const float t0 = w1.x * xs.x, t1 = w1.y * xs.y;
        const float t2 = w1.z * xs.z, t3 = w1.w * xs.w;
        ac.A[0] += t0 * yv0; ac.A[1]  += t0 * yv1; ac.A[2]  += t0 * yv2;
        ac.A[3] += t1 * yv0; ac.A[4]  += t1 * yv1; ac.A[5]  += t1 * yv2;
        ac.A[6] += t2 * yv0; ac.A[7]  += t2 * yv1; ac.A[8]  += t2 * yv2;
        ac.A[9] += t3 * yv0; ac.A[10] += t3 * yv1; ac.A[11] += t3 * yv2;

        // xv[v0] = (p0.x, p0.y, p1.x) ; xv[v1] = (p1.y, p2.x, p2.y)
        const float d0 = p0.x * yv0 + p0.y * yv1 + p1.x * yv2;
        const float d1 = p1.y * yv0 + p2.x * yv1 + p2.y * yv2;
        ac.ob0 += w3.x * d0 * INV_SQRT3;
        ac.ob1 += w3.y * d1 * INV_SQRT3;

        const float c0 = w2.x * ys, c1 = w2.y * ys;
        ac.B[0] += c0 * p0.x; ac.B[1] += c0 * p0.y; ac.B[2] += c0 * p1.x;
        ac.B[3] += c1 * p1.y; ac.B[4] += c1 * p2.x; ac.B[5] += c1 * p2.y;

        const float k0 = w4.x * INV_SQRT2, k1 = w4.y * INV_SQRT2;
        ac.C[0] += k0 * (p0.y * yv2 - p1.x * yv1);
        ac.C[1] += k0 * (p1.x * yv0 - p0.x * yv2);
        ac.C[2] += k0 * (p0.x * yv1 - p0.y * yv0);
        ac.C[3] += k1 * (p2.x * yv2 - p2.y * yv1);
        ac.C[4] += k1 * (p2.y * yv0 - p1.y * yv2);
        ac.C[5] += k1 * (p1.y * yv1 - p2.x * yv0);
    }
};

// ---------------------------------------------------------------------------
// Fused gather + depthwise TP + bias + equivariant LN. One warp per node.
// 2-edge manual unroll: 18 independent bulk loads in flight per stall point.
// ---------------------------------------------------------------------------
__global__ void __launch_bounds__(256, 2) fused_tp_ln_kernel(
    const float* __restrict__ node_feat,   // (N, 320)
    const float* __restrict__ edge_sh,     // (E, 4)
    const float* __restrict__ edge_weight, // (E, 448)
    const float* __restrict__ tp_bias,     // (192,)
    const int*   __restrict__ edge_src,
    const float* __restrict__ lnw,         // (448,)
    const float* __restrict__ lnb,         // (192,)
    float*       __restrict__ out,         // (N, 960)
    int n_nodes)
{
    const int warp = (blockIdx.x * blockDim.x + threadIdx.x) >> 5;
    const int lane = threadIdx.x & 31;
    if (warp >= n_nodes) return;
    const int node = warp;

    const int beg = g_start[node];
    const int end = g_start[node + 1];
    const int deg = end - beg;

    EdgeAcc ac;
    ac.a0x = ac.a0y = ac.a0z = ac.a0w = 0.f;
    ac.ob0 = ac.ob1 = 0.f;
#pragma unroll
    for (int i = 0; i < 12; i++) ac.A[i] = 0.f;
#pragma unroll
    for (int i = 0; i < 6; i++) { ac.B[i] = 0.f; ac.C[i] = 0.f; }

    int ei = beg;
    // 2-edge unrolled main loop
    for (; ei + 1 < end; ei += 2) {
        const int e0 = __ldg(g_sorted + ei);
        const int e1 = __ldg(g_sorted + ei + 1);
        const int s0 = __ldg(edge_src + e0);
        const int s1 = __ldg(edge_src + e1);

        EdgeData d0, d1;
        d0.load(node_feat, edge_sh, edge_weight, e0, s0, lane);
        d1.load(node_feat, edge_sh, edge_weight, e1, s1, lane);
        d0.accum(ac);
        d1.accum(ac);
    }
    // tail
    if (ei < end) {
        const int e0 = __ldg(g_sorted + ei);
        const int s0 = __ldg(edge_src + e0);
        EdgeData d0;
        d0.load(node_feat, edge_sh, edge_weight, e0, s0, lane);
        d0.accum(ac);
    }

    // per-edge bias, summed over deg edges
    const float fdeg = (float)deg;
    {
        const float4 b0 = __ldg(reinterpret_cast<const float4*>(tp_bias + 4 * lane));
        ac.a0x += fdeg * b0.x; ac.a0y += fdeg * b0.y;
        ac.a0z += fdeg * b0.z; ac.a0w += fdeg * b0.w;
        const float2 bb = __ldg(reinterpret_cast<const float2*>(tp_bias + 128 + 2 * lane));
        ac.ob0 += fdeg * bb.x; ac.ob1 += fdeg * bb.y;
    }

    // ---- equivariant LayerNorm on register-resident row ---------------------
    float s0 = ac.a0x + ac.a0y + ac.a0z + ac.a0w;
    float q0 = ac.a0x * ac.a0x + ac.a0y * ac.a0y + ac.a0z * ac.a0z + ac.a0w * ac.a0w;
    float s1 = ac.ob0 + ac.ob1;
    float q1 = ac.ob0 * ac.ob0 + ac.ob1 * ac.ob1;
    float q2 = 0.f, q3 = 0.f, q4 = 0.f;
#pragma unroll
    for (int i = 0; i < 12; i++) q2 += ac.A[i] * ac.A[i];
#pragma unroll
    for (int i = 0; i < 6; i++) { q3 += ac.B[i] * ac.B[i]; q4 += ac.C[i] * ac.C[i]; }

    s0 = warp_sum(s0); q0 = warp_sum(q0);
    s1 = warp_sum(s1); q1 = warp_sum(q1);
    q2 = warp_sum(q2); q3 = warp_sum(q3); q4 = warp_sum(q4);

    const float mu0 = s0 * (1.f / 128.f);
    const float r0  = rsqrtf(fmaxf(q0 * (1.f / 128.f) - mu0 * mu0, 0.f) + LN_EPS);
    const float mu1 = s1 * (1.f / 64.f);
    const float r1  = rsqrtf(fmaxf(q1 * (1.f / 64.f) - mu1 * mu1, 0.f) + LN_EPS);
    const float r2  = rsqrtf(q2 * (1.f / 384.f) + LN_EPS);
    const float r3  = rsqrtf(q3 * (1.f / 192.f) + LN_EPS);
    const float r4  = rsqrtf(q4 * (1.f / 192.f) + LN_EPS);

    float* row = out + (size_t)node * 960u;

    {   // field0
        const float4 wv = __ldg(reinterpret_cast<const float4*>(lnw + 4 * lane));
        const float4 bv = __ldg(reinterpret_cast<const float4*>(lnb + 4 * lane));
        float4 o;
        o.x = (ac.a0x - mu0) * r0 * wv.x + bv.x;
        o.y = (ac.a0y - mu0) * r0 * wv.y + bv.y;
        o.z = (ac.a0z - mu0) * r0 * wv.z + bv.z;
        o.w = (ac.a0w - mu0) * r0 * wv.w + bv.w;
        *reinterpret_cast<float4*>(row + 4 * lane) = o;
    }
    {   // field1
        const float2 wv = __ldg(reinterpret_cast<const float2*>(lnw + 128 + 2 * lane));
        const float2 bv = __ldg(reinterpret_cast<const float2*>(lnb + 128 + 2 * lane));
        float2 o;
        o.x = (ac.ob0 - mu1) * r1 * wv.x + bv.x;
        o.y = (ac.ob1 - mu1) * r1 * wv.y + bv.y;
        *reinterpret_cast<float2*>(row + 128 + 2 * lane) = o;
    }
    {   // field2: channels u = 4*lane + {0..3}
        const float4 wv = __ldg(reinterpret_cast<const float4*>(lnw + 192 + 4 * lane));
        const float sa = wv.x * r2, sb = wv.y * r2, sc = wv.z * r2, sd = wv.w * r2;
        float4 o1 = make_float4(ac.A[0] * sa, ac.A[1] * sa, ac.A[2]  * sa, ac.A[3]  * sb);
        float4 o2 = make_float4(ac.A[4] * sb, ac.A[5] * sb, ac.A[6]  * sc, ac.A[7]  * sc);
        float4 o3 = make_float4(ac.A[8] * sc, ac.A[9] * sd, ac.A[10] * sd, ac.A[11] * sd);
        *reinterpret_cast<float4*>(row + 192 + 12 * lane)     = o1;
        *reinterpret_cast<float4*>(row + 192 + 12 * lane + 4) = o2;
        *reinterpret_cast<float4*>(row + 192 + 12 * lane + 8) = o3;
    }
    {   // field3
        const float2 wv = __ldg(reinterpret_cast<const float2*>(lnw + 320 + 2 * lane));
        const float sa = wv.x * r3, sb = wv.y * r3;
        float2 o1 = make_float2(ac.B[0] * sa, ac.B[1] * sa);
        float2 o2 = make_float2(ac.B[2] * sa, ac.B[3] * sb);
        float2 o3 = make_float2(ac.B[4] * sb, ac.B[5] * sb);
        *reinterpret_cast<float2*>(row + 576 + 6 * lane)     = o1;
        *reinterpret_cast<float2*>(row + 576 + 6 * lane + 2) = o2;
        *reinterpret_cast<float2*>(row + 576 + 6 * lane + 4) = o3;
    }
    {   // field4
        const float2 wv = __ldg(reinterpret_cast<const float2*>(lnw + 384 + 2 * lane));
        const float sa = wv.x * r4, sb = wv.y * r4;
        float2 o1 = make_float2(ac.C[0] * sa, ac.C[1] * sa);
        float2 o2 = make_float2(ac.C[2] * sa, ac.C[3] * sb);
        float2 o3 = make_float2(ac.C[4] * sb, ac.C[5] * sb);
        *reinterpret_cast<float2*>(row + 768 + 6 * lane)     = o1;
        *reinterpret_cast<float2*>(row + 768 + 6 * lane + 2) = o2;
        *reinterpret_cast<float2*>(row + 768 + 6 * lane + 4) = o3;
    }
}

// ---------------------------------------------------------------------------
extern "C" void kernel_launch(void* const* d_in, const int* in_sizes, int n_in,
                              void* d_out, int out_size)
{
    const float* node_feat   = (const float*)d_in[0];
    const float* edge_sh     = (const float*)d_in[1];
    const float* edge_weight = (const float*)d_in[2];
    const float* tp_bias     = (const float*)d_in[3];
    const float* ln_weight   = (const float*)d_in[4];
    const float* ln_bias     = (const float*)d_in[5];
    const int*   edge_src    = (const int*)d_in[6];
    const int*   edge_dst    = (const int*)d_in[7];
    float* out = (float*)d_out;

    const int n_nodes = in_sizes[0] / 320;
    const int n_edges = in_sizes[7];

    hist_zero_kernel<<<(n_nodes + 255) / 256, 256>>>(n_nodes);
    {
        const int threads = (n_edges + 3) / 4;
        hist_count_kernel<<<(threads + 255) / 256, 256>>>(edge_dst, n_edges);
    }
    scan_kernel<<<1, 1024>>>(n_nodes);
    {
        const int threads = (n_edges + 3) / 4;
        scatter_kernel<<<(threads + 255) / 256, 256>>>(edge_dst, n_edges);
    }

    const int warps_per_block = 256 / 32;
    const int blocks = (n_nodes + warps_per_block - 1) / warps_per_block;
    fused_tp_ln_kernel<<<blocks, 256>>>(node_feat, edge_sh, edge_weight,
                                        tp_bias, edge_src, ln_weight, ln_bias,
                                        out, n_nodes);
}